// round 1
// baseline (speedup 1.0000x reference)
#include <cuda_runtime.h>
#include <math.h>

#define NN 10000
#define NE 640000
#define DH 128
#define NL 3

// ---------------- scratch (static device globals; no allocs) ----------------
__device__ int   g_cnt[NN];
__device__ int   g_off[NN + 1];
__device__ int   g_cur[NN];
__device__ int   g_srcs[NE];
__device__ float g_ws[NE];
__device__ float g_tmpA[NN * DH];
__device__ float g_tmpB[NN * DH];
__device__ float g_M[NN * DH];
__device__ float g_S[NN * DH];
__device__ float g_stmp[NL * NN * DH];
__device__ float g_scores[NL * NN];

// ---------------- preprocessing: CSR build (counting sort by dst) -----------
__global__ void zero_cnt_kernel() {
    int i = blockIdx.x * blockDim.x + threadIdx.x;
    if (i < NN) g_cnt[i] = 0;
}

__global__ void count_kernel(const int* __restrict__ ei) {
    int e = blockIdx.x * blockDim.x + threadIdx.x;
    if (e < NE) atomicAdd(&g_cnt[ei[NE + e]], 1);
}

__global__ void scan_kernel() {
    __shared__ int sh[1024];
    __shared__ int carry;
    if (threadIdx.x == 0) carry = 0;
    __syncthreads();
    for (int base = 0; base < NN; base += 1024) {
        int i = base + threadIdx.x;
        int v = (i < NN) ? g_cnt[i] : 0;
        sh[threadIdx.x] = v;
        __syncthreads();
        for (int o = 1; o < 1024; o <<= 1) {
            int t = (threadIdx.x >= o) ? sh[threadIdx.x - o] : 0;
            __syncthreads();
            sh[threadIdx.x] += t;
            __syncthreads();
        }
        if (i < NN) {
            int ex = carry + sh[threadIdx.x] - v;
            g_off[i] = ex;
            g_cur[i] = ex;
        }
        __syncthreads();
        if (threadIdx.x == 0) carry += sh[1023];
        __syncthreads();
    }
    if (threadIdx.x == 0) g_off[NN] = carry;  // == NE
}

__global__ void scatter_kernel(const int* __restrict__ ei, const float* __restrict__ conf) {
    int e = blockIdx.x * blockDim.x + threadIdx.x;
    if (e >= NE) return;
    int s = ei[e];
    int d = ei[NE + e];
    float w = expf(-fabsf(conf[s] - conf[d]));
    int pos = atomicAdd(&g_cur[d], 1);
    g_srcs[pos] = s;
    g_ws[pos] = w;
}

// ---------------- fp32 GEMM: C[M,128] = (A[M,128] @ B[128,128]) + bias ------
// BM=64, BN=128, BK=16, 128 threads, 8x8 register tile per thread.
// Column split per thread: cols {tx*4 .. tx*4+3} and {64+tx*4 .. 64+tx*4+3}
// (stride-64 split keeps Bs LDS.128 reads conflict-free).
__global__ void gemm128(const float* __restrict__ A, const float* __restrict__ B,
                        const float* __restrict__ bias, float* __restrict__ C,
                        int Mrows, int doRelu)
{
    __shared__ float As[16][68];   // padded, transposed: As[k][row]
    __shared__ float Bs[16][128];  // Bs[k][col]

    const int tid = threadIdx.x;     // 0..127
    const int ty  = tid >> 4;        // 0..7  -> rows ty*8 .. ty*8+7
    const int tx  = tid & 15;        // 0..15 -> col groups
    const int row0 = blockIdx.x * 64;

    float acc[8][8];
#pragma unroll
    for (int i = 0; i < 8; i++)
#pragma unroll
        for (int j = 0; j < 8; j++) acc[i][j] = 0.f;

    for (int k0 = 0; k0 < 128; k0 += 16) {
        // A tile: 64 rows x 16 cols = 256 float4; 2 per thread
#pragma unroll
        for (int it = 0; it < 2; it++) {
            int idx = tid + it * 128;
            int r  = idx >> 2;
            int c4 = (idx & 3) * 4;
            float4 v = make_float4(0.f, 0.f, 0.f, 0.f);
            int gr = row0 + r;
            if (gr < Mrows) v = *(const float4*)(A + (long)gr * 128 + k0 + c4);
            As[c4 + 0][r] = v.x;
            As[c4 + 1][r] = v.y;
            As[c4 + 2][r] = v.z;
            As[c4 + 3][r] = v.w;
        }
        // B tile: 16 rows x 128 cols = 512 float4; 4 per thread
#pragma unroll
        for (int it = 0; it < 4; it++) {
            int idx = tid + it * 128;
            int r  = idx >> 5;          // 0..15
            int c4 = (idx & 31) * 4;    // 0..124
            *(float4*)&Bs[r][c4] = *(const float4*)(B + (long)(k0 + r) * 128 + c4);
        }
        __syncthreads();

#pragma unroll
        for (int k = 0; k < 16; k++) {
            float a[8], b[8];
            *(float4*)&a[0] = *(const float4*)&As[k][ty * 8];
            *(float4*)&a[4] = *(const float4*)&As[k][ty * 8 + 4];
            *(float4*)&b[0] = *(const float4*)&Bs[k][tx * 4];
            *(float4*)&b[4] = *(const float4*)&Bs[k][64 + tx * 4];
#pragma unroll
            for (int i = 0; i < 8; i++)
#pragma unroll
                for (int j = 0; j < 8; j++) acc[i][j] += a[i] * b[j];
        }
        __syncthreads();
    }

    // epilogue: bias (+relu), vectorized stores
    float4 bi0 = *(const float4*)(bias + tx * 4);
    float4 bi1 = *(const float4*)(bias + 64 + tx * 4);
#pragma unroll
    for (int i = 0; i < 8; i++) {
        int gr = row0 + ty * 8 + i;
        if (gr >= Mrows) continue;
        float4 v0, v1;
        v0.x = acc[i][0] + bi0.x; v0.y = acc[i][1] + bi0.y;
        v0.z = acc[i][2] + bi0.z; v0.w = acc[i][3] + bi0.w;
        v1.x = acc[i][4] + bi1.x; v1.y = acc[i][5] + bi1.y;
        v1.z = acc[i][6] + bi1.z; v1.w = acc[i][7] + bi1.w;
        if (doRelu) {
            v0.x = fmaxf(v0.x, 0.f); v0.y = fmaxf(v0.y, 0.f);
            v0.z = fmaxf(v0.z, 0.f); v0.w = fmaxf(v0.w, 0.f);
            v1.x = fmaxf(v1.x, 0.f); v1.y = fmaxf(v1.y, 0.f);
            v1.z = fmaxf(v1.z, 0.f); v1.w = fmaxf(v1.w, 0.f);
        }
        *(float4*)(C + (long)gr * 128 + tx * 4)      = v0;
        *(float4*)(C + (long)gr * 128 + 64 + tx * 4) = v1;
    }
}

// ---------------- edge aggregation + self loop + relu -----------------------
// one warp per destination node; CSR-sorted edges -> no atomics.
__global__ void aggr_kernel(float* __restrict__ hout) {
    int gwarp = (blockIdx.x * blockDim.x + threadIdx.x) >> 5;
    int lane  = threadIdx.x & 31;
    if (gwarp >= NN) return;
    int beg = g_off[gwarp];
    int end = g_off[gwarp + 1];
    float4 acc = make_float4(0.f, 0.f, 0.f, 0.f);
    for (int e = beg; e < end; e++) {
        int s   = g_srcs[e];
        float w = g_ws[e];
        float4 m = *(const float4*)(g_M + (long)s * DH + lane * 4);
        acc.x += w * m.x; acc.y += w * m.y;
        acc.z += w * m.z; acc.w += w * m.w;
    }
    float4 sv = *(const float4*)(g_S + (long)gwarp * DH + lane * 4);
    float4 h;
    h.x = fmaxf(acc.x + sv.x, 0.f);
    h.y = fmaxf(acc.y + sv.y, 0.f);
    h.z = fmaxf(acc.z + sv.z, 0.f);
    h.w = fmaxf(acc.w + sv.w, 0.f);
    *(float4*)(hout + (long)gwarp * DH + lane * 4) = h;
}

// ---------------- score second layer: dot with W2[128] + b2 -----------------
__global__ void score_kernel(const float* __restrict__ W2, const float* __restrict__ b2) {
    int gwarp = (blockIdx.x * blockDim.x + threadIdx.x) >> 5;
    int lane  = threadIdx.x & 31;
    if (gwarp >= NL * NN) return;
    float4 t = *(const float4*)(g_stmp + (long)gwarp * DH + lane * 4);
    float4 w = *(const float4*)(W2 + lane * 4);
    float p = t.x * w.x + t.y * w.y + t.z * w.z + t.w * w.w;
#pragma unroll
    for (int o = 16; o > 0; o >>= 1) p += __shfl_xor_sync(0xffffffffu, p, o);
    if (lane == 0) g_scores[gwarp] = p + b2[0];
}

// ---------------- softmax over layers + weighted sum ------------------------
__global__ void final_kernel(const float* __restrict__ stacked,
                             float* __restrict__ out, float* __restrict__ lw) {
    int gwarp = (blockIdx.x * blockDim.x + threadIdx.x) >> 5;
    int lane  = threadIdx.x & 31;
    if (gwarp >= NN) return;
    float s0 = g_scores[gwarp];
    float s1 = g_scores[NN + gwarp];
    float s2 = g_scores[2 * NN + gwarp];
    float m  = fmaxf(s0, fmaxf(s1, s2));
    float e0 = expf(s0 - m), e1 = expf(s1 - m), e2 = expf(s2 - m);
    float inv = 1.f / (e0 + e1 + e2);
    float w0 = e0 * inv, w1 = e1 * inv, w2 = e2 * inv;
    float4 a = *(const float4*)(stacked + (long)gwarp * DH + lane * 4);
    float4 b = *(const float4*)(stacked + (long)NN * DH + (long)gwarp * DH + lane * 4);
    float4 c = *(const float4*)(stacked + 2L * NN * DH + (long)gwarp * DH + lane * 4);
    float4 o;
    o.x = w0 * a.x + w1 * b.x + w2 * c.x;
    o.y = w0 * a.y + w1 * b.y + w2 * c.y;
    o.z = w0 * a.z + w1 * b.z + w2 * c.z;
    o.w = w0 * a.w + w1 * b.w + w2 * c.w;
    *(float4*)(out + (long)gwarp * DH + lane * 4) = o;
    if (lane == 0) {
        lw[gwarp]          = w0;
        lw[NN + gwarp]     = w1;
        lw[2 * NN + gwarp] = w2;
    }
}

// ---------------- launch ----------------------------------------------------
extern "C" void kernel_launch(void* const* d_in, const int* in_sizes, int n_in,
                              void* d_out, int out_size) {
    const float* x       = (const float*)d_in[0];
    const int*   ei      = (const int*)  d_in[1];
    const float* conf    = (const float*)d_in[2];
    const float* msgW1   = (const float*)d_in[3];
    const float* msgb1   = (const float*)d_in[4];
    const float* msgW2   = (const float*)d_in[5];
    const float* msgb2   = (const float*)d_in[6];
    const float* selfW1  = (const float*)d_in[7];
    const float* selfb1  = (const float*)d_in[8];
    const float* selfW2  = (const float*)d_in[9];
    const float* selfb2  = (const float*)d_in[10];
    const float* scoreW1 = (const float*)d_in[11];
    const float* scoreb1 = (const float*)d_in[12];
    const float* scoreW2 = (const float*)d_in[13];
    const float* scoreb2 = (const float*)d_in[14];

    float* out     = (float*)d_out;                 // [NN, DH]
    float* stacked = out + (long)NN * DH;           // [NL, NN, DH]
    float* lw      = stacked + (long)NL * NN * DH;  // [NL, NN]

    // scratch addresses
    void *p_tmpA, *p_tmpB, *p_M, *p_S, *p_stmp;
    cudaGetSymbolAddress(&p_tmpA, g_tmpA);
    cudaGetSymbolAddress(&p_tmpB, g_tmpB);
    cudaGetSymbolAddress(&p_M, g_M);
    cudaGetSymbolAddress(&p_S, g_S);
    cudaGetSymbolAddress(&p_stmp, g_stmp);
    float* tmpA = (float*)p_tmpA;
    float* tmpB = (float*)p_tmpB;
    float* Mn   = (float*)p_M;
    float* Sn   = (float*)p_S;
    float* stmp = (float*)p_stmp;

    // CSR build
    zero_cnt_kernel<<<(NN + 255) / 256, 256>>>();
    count_kernel<<<(NE + 255) / 256, 256>>>(ei);
    scan_kernel<<<1, 1024>>>();
    scatter_kernel<<<(NE + 255) / 256, 256>>>(ei, conf);

    const int GB = (NN + 63) / 64;  // 157 blocks per node-GEMM
    const float* hin = x;
    for (int i = 0; i < NL; i++) {
        gemm128<<<GB, 128>>>(hin, msgW1 + (long)i * DH * DH, msgb1 + i * DH, tmpA, NN, 1);
        gemm128<<<GB, 128>>>(hin, selfW1 + (long)i * DH * DH, selfb1 + i * DH, tmpB, NN, 1);
        gemm128<<<GB, 128>>>(tmpA, msgW2 + (long)i * DH * DH, msgb2 + i * DH, Mn, NN, 0);
        gemm128<<<GB, 128>>>(tmpB, selfW2 + (long)i * DH * DH, selfb2 + i * DH, Sn, NN, 0);
        float* hout = stacked + (long)i * NN * DH;
        aggr_kernel<<<(NN + 7) / 8, 256>>>(hout);
        hin = hout;
    }

    // scoring
    gemm128<<<(NL * NN + 63) / 64, 128>>>(stacked, scoreW1, scoreb1, stmp, NL * NN, 1);
    score_kernel<<<(NL * NN + 7) / 8, 256>>>(scoreW2, scoreb2);
    final_kernel<<<(NN + 7) / 8, 256>>>(stacked, out, lw);
}

// round 3
// speedup vs baseline: 1.3727x; 1.3727x over previous
#include <cuda_runtime.h>
#include <cuda_bf16.h>
#include <cstdint>
#include <math.h>

#define NN 10000
#define NE 640000
#define DH 128
#define NL 3

// ---------------- scratch (static device globals; no allocs) ----------------
__device__ int   g_cnt[NN];
__device__ int   g_off[NN + 1];
__device__ int   g_cur[NN];
__device__ int   g_srcs[NE];
__device__ float g_ws[NE];
__device__ float g_tmpA[NN * DH];
__device__ float g_tmpB[NN * DH];
__device__ float g_M[NN * DH];
__device__ float g_S[NN * DH];
__device__ float g_scores[NL * NN];
__device__ float g_Wt[13 * DH * DH];   // pre-transposed weights: Wt[n][k] = W[k][n]

// ---------------- preprocessing: CSR build (counting sort by dst) -----------
__global__ void zero_kernel() {
    int i = blockIdx.x * blockDim.x + threadIdx.x;
    if (i < NN) g_cnt[i] = 0;
    if (i < NL * NN) g_scores[i] = 0.f;
}

__global__ void count_kernel(const int* __restrict__ ei) {
    int e = blockIdx.x * blockDim.x + threadIdx.x;
    if (e < NE) atomicAdd(&g_cnt[ei[NE + e]], 1);
}

__global__ void scan_kernel() {
    __shared__ int sh[1024];
    __shared__ int carry;
    if (threadIdx.x == 0) carry = 0;
    __syncthreads();
    for (int base = 0; base < NN; base += 1024) {
        int i = base + threadIdx.x;
        int v = (i < NN) ? g_cnt[i] : 0;
        sh[threadIdx.x] = v;
        __syncthreads();
        for (int o = 1; o < 1024; o <<= 1) {
            int t = (threadIdx.x >= o) ? sh[threadIdx.x - o] : 0;
            __syncthreads();
            sh[threadIdx.x] += t;
            __syncthreads();
        }
        if (i < NN) {
            int ex = carry + sh[threadIdx.x] - v;
            g_off[i] = ex;
            g_cur[i] = ex;
        }
        __syncthreads();
        if (threadIdx.x == 0) carry += sh[1023];
        __syncthreads();
    }
    if (threadIdx.x == 0) g_off[NN] = carry;
}

__global__ void scatter_kernel(const int* __restrict__ ei, const float* __restrict__ conf) {
    int e = blockIdx.x * blockDim.x + threadIdx.x;
    if (e >= NE) return;
    int s = ei[e];
    int d = ei[NE + e];
    float w = expf(-fabsf(conf[s] - conf[d]));
    int pos = atomicAdd(&g_cur[d], 1);
    g_srcs[pos] = s;
    g_ws[pos] = w;
}

// ---------------- weight pre-transpose: Wt[n][k] = W[k][n] ------------------
__global__ void transpose_weights(const float* __restrict__ msgW1, const float* __restrict__ selfW1,
                                  const float* __restrict__ msgW2, const float* __restrict__ selfW2,
                                  const float* __restrict__ scoreW1) {
    __shared__ float tile[32][33];
    int m = blockIdx.z;
    const float* src;
    if (m < 3)       src = msgW1  + (long)m * DH * DH;
    else if (m < 6)  src = selfW1 + (long)(m - 3) * DH * DH;
    else if (m < 9)  src = msgW2  + (long)(m - 6) * DH * DH;
    else if (m < 12) src = selfW2 + (long)(m - 9) * DH * DH;
    else             src = scoreW1;
    float* dst = g_Wt + (long)m * DH * DH;

    int x = blockIdx.x * 32 + threadIdx.x;
    int y = blockIdx.y * 32 + threadIdx.y;
#pragma unroll
    for (int j = 0; j < 32; j += 8)
        tile[threadIdx.y + j][threadIdx.x] = src[(y + j) * DH + x];
    __syncthreads();
    x = blockIdx.y * 32 + threadIdx.x;
    y = blockIdx.x * 32 + threadIdx.y;
#pragma unroll
    for (int j = 0; j < 32; j += 8)
        dst[(y + j) * DH + x] = tile[threadIdx.x][threadIdx.y + j];
}

// ================= mma.sync bf16 3x-split GEMM ==============================
// C[M,128] = A[M,128] @ W[128,128] (+bias), Bt = W^T row-major [n][k].
// mode 0: bias+relu store; mode 1: bias store; mode 2: relu(..+bias) dot w2 -> scores (atomic)
// SMEM tiles: bf16 [128][136] padded rows (272B stride -> conflict-free ldmatrix)
#define STRB 272                      // bytes per padded row
#define TILE_BYTES (128 * STRB)       // 34816
#define SM_BIAS  0
#define SM_W2    512
#define SM_A_HI  1024
#define SM_A_LO  (SM_A_HI + TILE_BYTES)
#define SM_B_HI  (SM_A_LO + TILE_BYTES)
#define SM_B_LO  (SM_B_HI + TILE_BYTES)
#define SM_TOTAL (SM_B_LO + TILE_BYTES)

#define LDSM_X4(r0, r1, r2, r3, addr) \
    asm volatile("ldmatrix.sync.aligned.m8n8.x4.shared.b16 {%0,%1,%2,%3}, [%4];" \
        : "=r"(r0), "=r"(r1), "=r"(r2), "=r"(r3) : "r"(addr))

#define MMA16816(d, a0, a1, a2, a3, b0, b1) \
    asm volatile("mma.sync.aligned.m16n8k16.row.col.f32.bf16.bf16.f32 " \
        "{%0,%1,%2,%3},{%4,%5,%6,%7},{%8,%9},{%0,%1,%2,%3};" \
        : "+f"((d)[0]), "+f"((d)[1]), "+f"((d)[2]), "+f"((d)[3]) \
        : "r"(a0), "r"(a1), "r"(a2), "r"(a3), "r"(b0), "r"(b1))

__device__ __forceinline__ uint32_t smem_u32(const void* p) {
    uint32_t a;
    asm("{ .reg .u64 t; cvta.to.shared.u64 t, %1; cvt.u32.u64 %0, t; }" : "=r"(a) : "l"(p));
    return a;
}

__device__ __forceinline__ uint32_t pack2bf(float x, float y) {
    __nv_bfloat162 h = __floats2bfloat162_rn(x, y);
    return *(uint32_t*)&h;
}

__global__ __launch_bounds__(256, 1)
void gemm_mma(const float* __restrict__ A, const float* __restrict__ Bt,
              const float* __restrict__ bias, float* __restrict__ C,
              int Mrows, int mode, const float* __restrict__ w2)
{
    extern __shared__ char smem[];
    const uint32_t sbase = smem_u32(smem);
    const int tid   = threadIdx.x;
    const int wid   = tid >> 5;
    const int lane  = tid & 31;
    const int warpM = wid & 3;          // 4 warps along M (32 rows each)
    const int warpN = wid >> 2;         // 2 warps along N (64 cols each)
    const int row0  = blockIdx.x * 128;
    float* bias_s = (float*)(smem + SM_BIAS);
    float* w2_s   = (float*)(smem + SM_W2);

    if (tid < 128) {
        bias_s[tid] = bias[tid];
        if (mode == 2) w2_s[tid] = w2[tid];
    }

    // ---- prologue: load fp32 tiles, split into bf16 hi/lo, store to smem ----
#pragma unroll 4
    for (int idx = tid; idx < 4096; idx += 256) {
        int r  = idx >> 5;
        int kb = (idx & 31) * 4;
        float4 v = make_float4(0.f, 0.f, 0.f, 0.f);
        if (row0 + r < Mrows) v = *(const float4*)(A + (long)(row0 + r) * DH + kb);
        float hx = __bfloat162float(__float2bfloat16_rn(v.x));
        float hy = __bfloat162float(__float2bfloat16_rn(v.y));
        float hz = __bfloat162float(__float2bfloat16_rn(v.z));
        float hw = __bfloat162float(__float2bfloat16_rn(v.w));
        uint32_t off = r * STRB + kb * 2;
        *(uint2*)(smem + SM_A_HI + off) = make_uint2(pack2bf(hx, hy), pack2bf(hz, hw));
        *(uint2*)(smem + SM_A_LO + off) = make_uint2(pack2bf(v.x - hx, v.y - hy), pack2bf(v.z - hz, v.w - hw));
    }
#pragma unroll 4
    for (int idx = tid; idx < 4096; idx += 256) {
        int r  = idx >> 5;
        int kb = (idx & 31) * 4;
        float4 v = *(const float4*)(Bt + (long)r * DH + kb);
        float hx = __bfloat162float(__float2bfloat16_rn(v.x));
        float hy = __bfloat162float(__float2bfloat16_rn(v.y));
        float hz = __bfloat162float(__float2bfloat16_rn(v.z));
        float hw = __bfloat162float(__float2bfloat16_rn(v.w));
        uint32_t off = r * STRB + kb * 2;
        *(uint2*)(smem + SM_B_HI + off) = make_uint2(pack2bf(hx, hy), pack2bf(hz, hw));
        *(uint2*)(smem + SM_B_LO + off) = make_uint2(pack2bf(v.x - hx, v.y - hy), pack2bf(v.z - hz, v.w - hw));
    }
    __syncthreads();

    // ---- per-thread ldmatrix base offsets ----
    const int grp = lane >> 3, r8 = lane & 7;
    // A mfrag (m16 x k16): lanes 0-7 rows m+0..7 k0-7 | 8-15 rows m+8..15 k0-7
    //                      | 16-23 rows m+0..7 k8-15 | 24-31 rows m+8..15 k8-15
    uint32_t aoff[2];
#pragma unroll
    for (int i = 0; i < 2; i++) {
        int mrow = warpM * 32 + i * 16 + ((grp & 1) << 3) + r8;
        aoff[i] = (uint32_t)(mrow * STRB + ((grp >> 1) ? 16 : 0));
    }
    // B nfrag-pair (two n8 x k16): lanes 0-7 n+0..7 k0-7 | 8-15 n+0..7 k8-15
    //                              | 16-23 n+8..15 k0-7 | 24-31 n+8..15 k8-15
    uint32_t boff[4];
#pragma unroll
    for (int jj = 0; jj < 4; jj++) {
        int nrow = warpN * 64 + jj * 16 + ((grp >> 1) << 3) + r8;
        boff[jj] = (uint32_t)(nrow * STRB + ((grp & 1) ? 16 : 0));
    }

    float acc[2][8][4];
#pragma unroll
    for (int i = 0; i < 2; i++)
#pragma unroll
        for (int j = 0; j < 8; j++)
#pragma unroll
            for (int q = 0; q < 4; q++) acc[i][j][q] = 0.f;

    // ---- main: 3 terms x 8 k-steps, 16 mma each ----
#pragma unroll
    for (int term = 0; term < 3; term++) {
        const uint32_t Ab = sbase + (term == 2 ? SM_A_LO : SM_A_HI);
        const uint32_t Bb = sbase + (term == 1 ? SM_B_LO : SM_B_HI);
#pragma unroll
        for (int ks = 0; ks < 8; ks++) {
            const uint32_t kb = ks * 32;   // 16 bf16 = 32 bytes
            uint32_t a[2][4];
#pragma unroll
            for (int i = 0; i < 2; i++)
                LDSM_X4(a[i][0], a[i][1], a[i][2], a[i][3], Ab + aoff[i] + kb);
            uint32_t b[4][4];
#pragma unroll
            for (int jj = 0; jj < 4; jj++)
                LDSM_X4(b[jj][0], b[jj][1], b[jj][2], b[jj][3], Bb + boff[jj] + kb);
#pragma unroll
            for (int i = 0; i < 2; i++)
#pragma unroll
                for (int j = 0; j < 8; j++)
                    MMA16816(acc[i][j], a[i][0], a[i][1], a[i][2], a[i][3],
                             b[j >> 1][(j & 1) * 2], b[j >> 1][(j & 1) * 2 + 1]);
        }
    }

    // ---- epilogue ----
    const int rbase = row0 + warpM * 32 + (lane >> 2);
    const int cbase = warpN * 64 + (lane & 3) * 2;
    if (mode == 2) {
        float dot[2][2] = {{0.f, 0.f}, {0.f, 0.f}};
#pragma unroll
        for (int i = 0; i < 2; i++)
#pragma unroll
            for (int j = 0; j < 8; j++) {
                int cc = cbase + j * 8;
                float b0 = bias_s[cc], b1 = bias_s[cc + 1];
                float w0 = w2_s[cc],   w1 = w2_s[cc + 1];
                dot[i][0] += fmaxf(acc[i][j][0] + b0, 0.f) * w0 + fmaxf(acc[i][j][1] + b1, 0.f) * w1;
                dot[i][1] += fmaxf(acc[i][j][2] + b0, 0.f) * w0 + fmaxf(acc[i][j][3] + b1, 0.f) * w1;
            }
#pragma unroll
        for (int i = 0; i < 2; i++)
#pragma unroll
            for (int hh = 0; hh < 2; hh++) {
                float v = dot[i][hh];
                v += __shfl_xor_sync(0xffffffffu, v, 1);
                v += __shfl_xor_sync(0xffffffffu, v, 2);
                int rr = rbase + i * 16 + hh * 8;
                if ((lane & 3) == 0 && rr < Mrows) atomicAdd(&C[rr], v);
            }
    } else {
#pragma unroll
        for (int i = 0; i < 2; i++)
#pragma unroll
            for (int j = 0; j < 8; j++) {
                int cc = cbase + j * 8;
                float b0 = bias_s[cc], b1 = bias_s[cc + 1];
                float v0 = acc[i][j][0] + b0, v1 = acc[i][j][1] + b1;
                float v2 = acc[i][j][2] + b0, v3 = acc[i][j][3] + b1;
                if (mode == 0) {
                    v0 = fmaxf(v0, 0.f); v1 = fmaxf(v1, 0.f);
                    v2 = fmaxf(v2, 0.f); v3 = fmaxf(v3, 0.f);
                }
                int rr = rbase + i * 16;
                if (rr < Mrows)     *(float2*)(C + (long)rr * DH + cc)       = make_float2(v0, v1);
                if (rr + 8 < Mrows) *(float2*)(C + (long)(rr + 8) * DH + cc) = make_float2(v2, v3);
            }
    }
}

// ---------------- edge aggregation + self loop + relu -----------------------
__global__ void aggr_kernel(float* __restrict__ hout) {
    int gwarp = (blockIdx.x * blockDim.x + threadIdx.x) >> 5;
    int lane  = threadIdx.x & 31;
    if (gwarp >= NN) return;
    int beg = g_off[gwarp];
    int end = g_off[gwarp + 1];
    float4 acc = make_float4(0.f, 0.f, 0.f, 0.f);
    for (int e = beg; e < end; e++) {
        int s   = g_srcs[e];
        float w = g_ws[e];
        float4 m = *(const float4*)(g_M + (long)s * DH + lane * 4);
        acc.x += w * m.x; acc.y += w * m.y;
        acc.z += w * m.z; acc.w += w * m.w;
    }
    float4 sv = *(const float4*)(g_S + (long)gwarp * DH + lane * 4);
    float4 h;
    h.x = fmaxf(acc.x + sv.x, 0.f);
    h.y = fmaxf(acc.y + sv.y, 0.f);
    h.z = fmaxf(acc.z + sv.z, 0.f);
    h.w = fmaxf(acc.w + sv.w, 0.f);
    *(float4*)(hout + (long)gwarp * DH + lane * 4) = h;
}

// ---------------- softmax over layers + weighted sum ------------------------
// (score_b2 omitted: softmax over layers is invariant to a constant shift)
__global__ void final_kernel(const float* __restrict__ stacked,
                             float* __restrict__ out, float* __restrict__ lw) {
    int gwarp = (blockIdx.x * blockDim.x + threadIdx.x) >> 5;
    int lane  = threadIdx.x & 31;
    if (gwarp >= NN) return;
    float s0 = g_scores[gwarp];
    float s1 = g_scores[NN + gwarp];
    float s2 = g_scores[2 * NN + gwarp];
    float m  = fmaxf(s0, fmaxf(s1, s2));
    float e0 = expf(s0 - m), e1 = expf(s1 - m), e2 = expf(s2 - m);
    float inv = 1.f / (e0 + e1 + e2);
    float w0 = e0 * inv, w1 = e1 * inv, w2 = e2 * inv;
    float4 a = *(const float4*)(stacked + (long)gwarp * DH + lane * 4);
    float4 b = *(const float4*)(stacked + (long)NN * DH + (long)gwarp * DH + lane * 4);
    float4 c = *(const float4*)(stacked + 2L * NN * DH + (long)gwarp * DH + lane * 4);
    float4 o;
    o.x = w0 * a.x + w1 * b.x + w2 * c.x;
    o.y = w0 * a.y + w1 * b.y + w2 * c.y;
    o.z = w0 * a.z + w1 * b.z + w2 * c.z;
    o.w = w0 * a.w + w1 * b.w + w2 * c.w;
    *(float4*)(out + (long)gwarp * DH + lane * 4) = o;
    if (lane == 0) {
        lw[gwarp]          = w0;
        lw[NN + gwarp]     = w1;
        lw[2 * NN + gwarp] = w2;
    }
}

// ---------------- launch ----------------------------------------------------
extern "C" void kernel_launch(void* const* d_in, const int* in_sizes, int n_in,
                              void* d_out, int out_size) {
    const float* x       = (const float*)d_in[0];
    const int*   ei      = (const int*)  d_in[1];
    const float* conf    = (const float*)d_in[2];
    const float* msgb1   = (const float*)d_in[4];
    const float* msgb2   = (const float*)d_in[6];
    const float* selfb1  = (const float*)d_in[8];
    const float* selfb2  = (const float*)d_in[10];
    const float* scoreb1 = (const float*)d_in[12];
    const float* scoreW2 = (const float*)d_in[13];

    float* out     = (float*)d_out;                 // [NN, DH]
    float* stacked = out + (long)NN * DH;           // [NL, NN, DH]
    float* lw      = stacked + (long)NL * NN * DH;  // [NL, NN]

    void *p_tmpA, *p_tmpB, *p_M, *p_S, *p_Wt, *p_scores;
    cudaGetSymbolAddress(&p_tmpA, g_tmpA);
    cudaGetSymbolAddress(&p_tmpB, g_tmpB);
    cudaGetSymbolAddress(&p_M, g_M);
    cudaGetSymbolAddress(&p_S, g_S);
    cudaGetSymbolAddress(&p_Wt, g_Wt);
    cudaGetSymbolAddress(&p_scores, g_scores);
    float* tmpA   = (float*)p_tmpA;
    float* tmpB   = (float*)p_tmpB;
    float* Mn     = (float*)p_M;
    float* Sn     = (float*)p_S;
    float* Wt     = (float*)p_Wt;
    float* scores = (float*)p_scores;

    cudaFuncSetAttribute(gemm_mma, cudaFuncAttributeMaxDynamicSharedMemorySize, SM_TOTAL);

    // CSR build + weight transpose + zero scores
    zero_kernel<<<(NL * NN + 255) / 256, 256>>>();
    count_kernel<<<(NE + 255) / 256, 256>>>(ei);
    transpose_weights<<<dim3(4, 4, 13), dim3(32, 8)>>>((const float*)d_in[3], (const float*)d_in[7],
                                                       (const float*)d_in[5], (const float*)d_in[9],
                                                       (const float*)d_in[11]);
    scan_kernel<<<1, 1024>>>();
    scatter_kernel<<<(NE + 255) / 256, 256>>>(ei, conf);

    const int GB = (NN + 127) / 128;  // 79 CTAs
    const float* hin = x;
    for (int i = 0; i < NL; i++) {
        gemm_mma<<<GB, 256, SM_TOTAL>>>(hin,  Wt + (long)(0 + i) * DH * DH, msgb1  + i * DH, tmpA, NN, 0, nullptr);
        gemm_mma<<<GB, 256, SM_TOTAL>>>(hin,  Wt + (long)(3 + i) * DH * DH, selfb1 + i * DH, tmpB, NN, 0, nullptr);
        gemm_mma<<<GB, 256, SM_TOTAL>>>(tmpA, Wt + (long)(6 + i) * DH * DH, msgb2  + i * DH, Mn,   NN, 1, nullptr);
        gemm_mma<<<GB, 256, SM_TOTAL>>>(tmpB, Wt + (long)(9 + i) * DH * DH, selfb2 + i * DH, Sn,   NN, 1, nullptr);
        float* hout = stacked + (long)i * NN * DH;
        aggr_kernel<<<(NN + 7) / 8, 256>>>(hout);
        hin = hout;
    }

    // scoring: fused Linear->ReLU->dot(W2) into GEMM epilogue (b2 dropped: softmax shift-invariant)
    gemm_mma<<<(NL * NN + 127) / 128, 256, SM_TOTAL>>>(stacked, Wt + 12L * DH * DH, scoreb1,
                                                       scores, NL * NN, 2, scoreW2);
    final_kernel<<<(NN + 7) / 8, 256>>>(stacked, out, lw);
}

// round 4
// speedup vs baseline: 1.6185x; 1.1791x over previous
#include <cuda_runtime.h>
#include <cuda_bf16.h>
#include <cuda_fp16.h>
#include <cstdint>
#include <math.h>

#define NN 10000
#define NE 640000
#define DH 128
#define NL 3

// ---------------- scratch (static device globals; no allocs) ----------------
__device__ int    g_cnt[NN];
__device__ int    g_off[NN + 1];
__device__ int    g_pos[NE];
__device__ int2   g_edge[NE];          // packed (src, w-as-bits), CSR order by dst
__device__ float  g_tmpA[NN * DH];
__device__ float  g_tmpB[NN * DH];
__device__ __half g_Mh[NN * DH];       // fp16 message buffer
__device__ float  g_S[NN * DH];
__device__ float  g_scores[NL * NN];
__device__ float  g_Wt[13 * DH * DH];  // pre-transposed weights: Wt[n][k] = W[k][n]

// ---------------- preprocessing ---------------------------------------------
__global__ void zero_kernel() {
    int i = blockIdx.x * blockDim.x + threadIdx.x;
    if (i < NN) g_cnt[i] = 0;
    if (i < NL * NN) g_scores[i] = 0.f;
}

__global__ void count_kernel(const int* __restrict__ ei) {
    int e = blockIdx.x * blockDim.x + threadIdx.x;
    if (e < NE) g_pos[e] = atomicAdd(&g_cnt[ei[NE + e]], 1);
}

// 1024 threads, 10 elems/thread: sequential + warp scan + cross-warp scan
__global__ void scan_kernel() {
    __shared__ int wsum[32];
    int t = threadIdx.x;
    int lane = t & 31, w = t >> 5;
    int base = t * 10;
    int loc[10];
    int s = 0;
#pragma unroll
    for (int i = 0; i < 10; i++) {
        int idx = base + i;
        int c = (idx < NN) ? g_cnt[idx] : 0;
        loc[i] = s; s += c;
    }
    int inc = s;
#pragma unroll
    for (int o = 1; o < 32; o <<= 1) {
        int u = __shfl_up_sync(0xffffffffu, inc, o);
        if (lane >= o) inc += u;
    }
    if (lane == 31) wsum[w] = inc;
    __syncthreads();
    if (w == 0) {
        int ws = wsum[lane];
#pragma unroll
        for (int o = 1; o < 32; o <<= 1) {
            int u = __shfl_up_sync(0xffffffffu, ws, o);
            if (lane >= o) ws += u;
        }
        wsum[lane] = ws;
    }
    __syncthreads();
    int warp_excl = (w == 0) ? 0 : wsum[w - 1];
    int excl = warp_excl + (inc - s);
#pragma unroll
    for (int i = 0; i < 10; i++) {
        int idx = base + i;
        if (idx < NN) g_off[idx] = excl + loc[i];
    }
    if (t == 1023) g_off[NN] = warp_excl + inc;
}

__global__ void scatter_kernel(const int* __restrict__ ei, const float* __restrict__ conf) {
    int e = blockIdx.x * blockDim.x + threadIdx.x;
    if (e >= NE) return;
    int s = ei[e];
    int d = ei[NE + e];
    float w = expf(-fabsf(conf[s] - conf[d]));
    int p = g_off[d] + g_pos[e];
    g_edge[p] = make_int2(s, __float_as_int(w));
}

// ---------------- weight pre-transpose: Wt[n][k] = W[k][n] ------------------
__global__ void transpose_weights(const float* __restrict__ msgW1, const float* __restrict__ selfW1,
                                  const float* __restrict__ msgW2, const float* __restrict__ selfW2,
                                  const float* __restrict__ scoreW1) {
    __shared__ float tile[32][33];
    int m = blockIdx.z;
    const float* src;
    if (m < 3)       src = msgW1  + (long)m * DH * DH;
    else if (m < 6)  src = selfW1 + (long)(m - 3) * DH * DH;
    else if (m < 9)  src = msgW2  + (long)(m - 6) * DH * DH;
    else if (m < 12) src = selfW2 + (long)(m - 9) * DH * DH;
    else             src = scoreW1;
    float* dst = g_Wt + (long)m * DH * DH;

    int x = blockIdx.x * 32 + threadIdx.x;
    int y = blockIdx.y * 32 + threadIdx.y;
#pragma unroll
    for (int j = 0; j < 32; j += 8)
        tile[threadIdx.y + j][threadIdx.x] = src[(y + j) * DH + x];
    __syncthreads();
    x = blockIdx.y * 32 + threadIdx.x;
    y = blockIdx.x * 32 + threadIdx.y;
#pragma unroll
    for (int j = 0; j < 32; j += 8)
        dst[(y + j) * DH + x] = tile[threadIdx.x][threadIdx.y + j];
}

// ================= fused dual-output mma.sync bf16 3x-split GEMM ============
// Two independent GEMMs in one launch (blockIdx < nblk0 -> half 0).
// C[M,128] = A[M,128] @ W[128,128] (+bias); Bt row-major [n][k] = W^T.
// mode 0: bias+relu fp32; mode 1: bias fp32; mode 2: relu(+bias) dot w2 -> scores (atomic);
// mode 3: bias fp16 store.
#define STRB 272
#define TILE_BYTES (128 * STRB)
#define SM_BIAS  0
#define SM_W2    512
#define SM_A_HI  1024
#define SM_A_LO  (SM_A_HI + TILE_BYTES)
#define SM_B_HI  (SM_A_LO + TILE_BYTES)
#define SM_B_LO  (SM_B_HI + TILE_BYTES)
#define SM_TOTAL (SM_B_LO + TILE_BYTES)

#define LDSM_X4(r0, r1, r2, r3, addr) \
    asm volatile("ldmatrix.sync.aligned.m8n8.x4.shared.b16 {%0,%1,%2,%3}, [%4];" \
        : "=r"(r0), "=r"(r1), "=r"(r2), "=r"(r3) : "r"(addr))

#define MMA16816(d, a0, a1, a2, a3, b0, b1) \
    asm volatile("mma.sync.aligned.m16n8k16.row.col.f32.bf16.bf16.f32 " \
        "{%0,%1,%2,%3},{%4,%5,%6,%7},{%8,%9},{%0,%1,%2,%3};" \
        : "+f"((d)[0]), "+f"((d)[1]), "+f"((d)[2]), "+f"((d)[3]) \
        : "r"(a0), "r"(a1), "r"(a2), "r"(a3), "r"(b0), "r"(b1))

__device__ __forceinline__ uint32_t smem_u32(const void* p) {
    uint32_t a;
    asm("{ .reg .u64 t; cvta.to.shared.u64 t, %1; cvt.u32.u64 %0, t; }" : "=r"(a) : "l"(p));
    return a;
}
__device__ __forceinline__ uint32_t pack2bf(float x, float y) {
    __nv_bfloat162 h = __floats2bfloat162_rn(x, y);
    return *(uint32_t*)&h;
}

__global__ __launch_bounds__(512, 1)
void gemm_mma(const float* __restrict__ A0, const float* __restrict__ Bt0,
              const float* __restrict__ bias0, void* __restrict__ C0, int M0, int mode0,
              const float* __restrict__ A1, const float* __restrict__ Bt1,
              const float* __restrict__ bias1, void* __restrict__ C1, int M1, int mode1,
              int nblk0, const float* __restrict__ w2)
{
    extern __shared__ char smem[];
    const uint32_t sbase = smem_u32(smem);
    const int tid   = threadIdx.x;
    const int wid   = tid >> 5;
    const int lane  = tid & 31;
    const int warpM = wid & 3;     // 4 warps along M (32 rows each)
    const int warpN = wid >> 2;    // 4 warps along N (32 cols each)

    const int sel = (blockIdx.x >= nblk0);
    const float* A    = sel ? A1 : A0;
    const float* Bt   = sel ? Bt1 : Bt0;
    const float* bias = sel ? bias1 : bias0;
    void* C           = sel ? C1 : C0;
    const int Mrows   = sel ? M1 : M0;
    const int mode    = sel ? mode1 : mode0;
    const int row0    = (sel ? (blockIdx.x - nblk0) : blockIdx.x) * 128;

    float* bias_s = (float*)(smem + SM_BIAS);
    float* w2_s   = (float*)(smem + SM_W2);
    if (tid < 128) {
        bias_s[tid] = bias[tid];
        if (mode == 2) w2_s[tid] = w2[tid];
    }

    // ---- prologue: fp32 -> bf16 hi/lo split into smem ----
#pragma unroll
    for (int idx = tid; idx < 4096; idx += 512) {
        int r  = idx >> 5;
        int kb = (idx & 31) * 4;
        float4 v = make_float4(0.f, 0.f, 0.f, 0.f);
        if (row0 + r < Mrows) v = *(const float4*)(A + (long)(row0 + r) * DH + kb);
        float hx = __bfloat162float(__float2bfloat16_rn(v.x));
        float hy = __bfloat162float(__float2bfloat16_rn(v.y));
        float hz = __bfloat162float(__float2bfloat16_rn(v.z));
        float hw = __bfloat162float(__float2bfloat16_rn(v.w));
        uint32_t off = r * STRB + kb * 2;
        *(uint2*)(smem + SM_A_HI + off) = make_uint2(pack2bf(hx, hy), pack2bf(hz, hw));
        *(uint2*)(smem + SM_A_LO + off) = make_uint2(pack2bf(v.x - hx, v.y - hy), pack2bf(v.z - hz, v.w - hw));
    }
#pragma unroll
    for (int idx = tid; idx < 4096; idx += 512) {
        int r  = idx >> 5;
        int kb = (idx & 31) * 4;
        float4 v = *(const float4*)(Bt + (long)r * DH + kb);
        float hx = __bfloat162float(__float2bfloat16_rn(v.x));
        float hy = __bfloat162float(__float2bfloat16_rn(v.y));
        float hz = __bfloat162float(__float2bfloat16_rn(v.z));
        float hw = __bfloat162float(__float2bfloat16_rn(v.w));
        uint32_t off = r * STRB + kb * 2;
        *(uint2*)(smem + SM_B_HI + off) = make_uint2(pack2bf(hx, hy), pack2bf(hz, hw));
        *(uint2*)(smem + SM_B_LO + off) = make_uint2(pack2bf(v.x - hx, v.y - hy), pack2bf(v.z - hz, v.w - hw));
    }
    __syncthreads();

    // ---- ldmatrix per-thread offsets ----
    const int grp = lane >> 3, r8 = lane & 7;
    uint32_t aoff[2];
#pragma unroll
    for (int i = 0; i < 2; i++) {
        int mrow = warpM * 32 + i * 16 + ((grp & 1) << 3) + r8;
        aoff[i] = (uint32_t)(mrow * STRB + ((grp >> 1) ? 16 : 0));
    }
    uint32_t boff[2];
#pragma unroll
    for (int jj = 0; jj < 2; jj++) {
        int nrow = warpN * 32 + jj * 16 + ((grp >> 1) << 3) + r8;
        boff[jj] = (uint32_t)(nrow * STRB + ((grp & 1) ? 16 : 0));
    }

    float acc[2][4][4];
#pragma unroll
    for (int i = 0; i < 2; i++)
#pragma unroll
        for (int j = 0; j < 4; j++)
#pragma unroll
            for (int q = 0; q < 4; q++) acc[i][j][q] = 0.f;

    // ---- main: 3 split terms x 8 k-steps ----
#pragma unroll
    for (int term = 0; term < 3; term++) {
        const uint32_t Ab = sbase + (term == 2 ? SM_A_LO : SM_A_HI);
        const uint32_t Bb = sbase + (term == 1 ? SM_B_LO : SM_B_HI);
#pragma unroll
        for (int ks = 0; ks < 8; ks++) {
            const uint32_t kb = ks * 32;
            uint32_t a[2][4];
#pragma unroll
            for (int i = 0; i < 2; i++)
                LDSM_X4(a[i][0], a[i][1], a[i][2], a[i][3], Ab + aoff[i] + kb);
            uint32_t b[2][4];
#pragma unroll
            for (int jj = 0; jj < 2; jj++)
                LDSM_X4(b[jj][0], b[jj][1], b[jj][2], b[jj][3], Bb + boff[jj] + kb);
#pragma unroll
            for (int i = 0; i < 2; i++)
#pragma unroll
                for (int j = 0; j < 4; j++)
                    MMA16816(acc[i][j], a[i][0], a[i][1], a[i][2], a[i][3],
                             b[j >> 1][(j & 1) * 2], b[j >> 1][(j & 1) * 2 + 1]);
        }
    }

    // ---- epilogue ----
    const int rbase = row0 + warpM * 32 + (lane >> 2);
    const int cbase = warpN * 32 + (lane & 3) * 2;
    if (mode == 2) {
        float* Cs = (float*)C;
        float dot[2][2] = {{0.f, 0.f}, {0.f, 0.f}};
#pragma unroll
        for (int i = 0; i < 2; i++)
#pragma unroll
            for (int j = 0; j < 4; j++) {
                int cc = cbase + j * 8;
                float b0 = bias_s[cc], b1 = bias_s[cc + 1];
                float w0 = w2_s[cc],   w1 = w2_s[cc + 1];
                dot[i][0] += fmaxf(acc[i][j][0] + b0, 0.f) * w0 + fmaxf(acc[i][j][1] + b1, 0.f) * w1;
                dot[i][1] += fmaxf(acc[i][j][2] + b0, 0.f) * w0 + fmaxf(acc[i][j][3] + b1, 0.f) * w1;
            }
#pragma unroll
        for (int i = 0; i < 2; i++)
#pragma unroll
            for (int hh = 0; hh < 2; hh++) {
                float v = dot[i][hh];
                v += __shfl_xor_sync(0xffffffffu, v, 1);
                v += __shfl_xor_sync(0xffffffffu, v, 2);
                int rr = rbase + i * 16 + hh * 8;
                if ((lane & 3) == 0 && rr < Mrows) atomicAdd(&Cs[rr], v);
            }
    } else if (mode == 3) {
        __half* Ch = (__half*)C;
#pragma unroll
        for (int i = 0; i < 2; i++)
#pragma unroll
            for (int j = 0; j < 4; j++) {
                int cc = cbase + j * 8;
                float b0 = bias_s[cc], b1 = bias_s[cc + 1];
                int rr = rbase + i * 16;
                if (rr < Mrows)
                    *(__half2*)(Ch + (long)rr * DH + cc) =
                        __floats2half2_rn(acc[i][j][0] + b0, acc[i][j][1] + b1);
                if (rr + 8 < Mrows)
                    *(__half2*)(Ch + (long)(rr + 8) * DH + cc) =
                        __floats2half2_rn(acc[i][j][2] + b0, acc[i][j][3] + b1);
            }
    } else {
        float* Cf = (float*)C;
#pragma unroll
        for (int i = 0; i < 2; i++)
#pragma unroll
            for (int j = 0; j < 4; j++) {
                int cc = cbase + j * 8;
                float b0 = bias_s[cc], b1 = bias_s[cc + 1];
                float v0 = acc[i][j][0] + b0, v1 = acc[i][j][1] + b1;
                float v2 = acc[i][j][2] + b0, v3 = acc[i][j][3] + b1;
                if (mode == 0) {
                    v0 = fmaxf(v0, 0.f); v1 = fmaxf(v1, 0.f);
                    v2 = fmaxf(v2, 0.f); v3 = fmaxf(v3, 0.f);
                }
                int rr = rbase + i * 16;
                if (rr < Mrows)     *(float2*)(Cf + (long)rr * DH + cc)       = make_float2(v0, v1);
                if (rr + 8 < Mrows) *(float2*)(Cf + (long)(rr + 8) * DH + cc) = make_float2(v2, v3);
            }
    }
}

// ---------------- edge aggregation (fp16 messages) + self loop + relu -------
__global__ void aggr_kernel(float* __restrict__ hout) {
    int node = (blockIdx.x * blockDim.x + threadIdx.x) >> 5;
    int lane = threadIdx.x & 31;
    if (node >= NN) return;
    int beg = g_off[node];
    int end = g_off[node + 1];
    float a0 = 0.f, a1 = 0.f, a2 = 0.f, a3 = 0.f;
    int e = beg;
    for (; e + 1 < end; e += 2) {
        int2 ed0 = g_edge[e];
        int2 ed1 = g_edge[e + 1];
        uint2 r0 = *(const uint2*)(g_Mh + (long)ed0.x * DH + lane * 4);
        uint2 r1 = *(const uint2*)(g_Mh + (long)ed1.x * DH + lane * 4);
        float w0 = __int_as_float(ed0.y), w1 = __int_as_float(ed1.y);
        float2 p0 = __half22float2(*(__half2*)&r0.x);
        float2 p1 = __half22float2(*(__half2*)&r0.y);
        float2 q0 = __half22float2(*(__half2*)&r1.x);
        float2 q1 = __half22float2(*(__half2*)&r1.y);
        a0 += w0 * p0.x + w1 * q0.x;
        a1 += w0 * p0.y + w1 * q0.y;
        a2 += w0 * p1.x + w1 * q1.x;
        a3 += w0 * p1.y + w1 * q1.y;
    }
    if (e < end) {
        int2 ed = g_edge[e];
        uint2 r0 = *(const uint2*)(g_Mh + (long)ed.x * DH + lane * 4);
        float w = __int_as_float(ed.y);
        float2 p0 = __half22float2(*(__half2*)&r0.x);
        float2 p1 = __half22float2(*(__half2*)&r0.y);
        a0 += w * p0.x; a1 += w * p0.y; a2 += w * p1.x; a3 += w * p1.y;
    }
    float4 sv = *(const float4*)(g_S + (long)node * DH + lane * 4);
    float4 h;
    h.x = fmaxf(a0 + sv.x, 0.f);
    h.y = fmaxf(a1 + sv.y, 0.f);
    h.z = fmaxf(a2 + sv.z, 0.f);
    h.w = fmaxf(a3 + sv.w, 0.f);
    *(float4*)(hout + (long)node * DH + lane * 4) = h;
}

// ---------------- softmax over layers + weighted sum ------------------------
// (score_b2 omitted: softmax over layers is shift-invariant)
__global__ void final_kernel(const float* __restrict__ stacked,
                             float* __restrict__ out, float* __restrict__ lw) {
    int node = (blockIdx.x * blockDim.x + threadIdx.x) >> 5;
    int lane = threadIdx.x & 31;
    if (node >= NN) return;
    float s0 = g_scores[node];
    float s1 = g_scores[NN + node];
    float s2 = g_scores[2 * NN + node];
    float m  = fmaxf(s0, fmaxf(s1, s2));
    float e0 = expf(s0 - m), e1 = expf(s1 - m), e2 = expf(s2 - m);
    float inv = 1.f / (e0 + e1 + e2);
    float w0 = e0 * inv, w1 = e1 * inv, w2 = e2 * inv;
    float4 a = *(const float4*)(stacked + (long)node * DH + lane * 4);
    float4 b = *(const float4*)(stacked + (long)NN * DH + (long)node * DH + lane * 4);
    float4 c = *(const float4*)(stacked + 2L * NN * DH + (long)node * DH + lane * 4);
    float4 o;
    o.x = w0 * a.x + w1 * b.x + w2 * c.x;
    o.y = w0 * a.y + w1 * b.y + w2 * c.y;
    o.z = w0 * a.z + w1 * b.z + w2 * c.z;
    o.w = w0 * a.w + w1 * b.w + w2 * c.w;
    *(float4*)(out + (long)node * DH + lane * 4) = o;
    if (lane == 0) {
        lw[node]          = w0;
        lw[NN + node]     = w1;
        lw[2 * NN + node] = w2;
    }
}

// ---------------- launch ----------------------------------------------------
extern "C" void kernel_launch(void* const* d_in, const int* in_sizes, int n_in,
                              void* d_out, int out_size) {
    const float* x       = (const float*)d_in[0];
    const int*   ei      = (const int*)  d_in[1];
    const float* conf    = (const float*)d_in[2];
    const float* msgb1   = (const float*)d_in[4];
    const float* msgb2   = (const float*)d_in[6];
    const float* selfb1  = (const float*)d_in[8];
    const float* selfb2  = (const float*)d_in[10];
    const float* scoreb1 = (const float*)d_in[12];
    const float* scoreW2 = (const float*)d_in[13];

    float* out     = (float*)d_out;                 // [NN, DH]
    float* stacked = out + (long)NN * DH;           // [NL, NN, DH]
    float* lw      = stacked + (long)NL * NN * DH;  // [NL, NN]

    void *p_tmpA, *p_tmpB, *p_Mh, *p_S, *p_Wt, *p_scores;
    cudaGetSymbolAddress(&p_tmpA, g_tmpA);
    cudaGetSymbolAddress(&p_tmpB, g_tmpB);
    cudaGetSymbolAddress(&p_Mh, g_Mh);
    cudaGetSymbolAddress(&p_S, g_S);
    cudaGetSymbolAddress(&p_Wt, g_Wt);
    cudaGetSymbolAddress(&p_scores, g_scores);
    float*  tmpA   = (float*)p_tmpA;
    float*  tmpB   = (float*)p_tmpB;
    __half* Mh     = (__half*)p_Mh;
    float*  Sn     = (float*)p_S;
    float*  Wt     = (float*)p_Wt;
    float*  scores = (float*)p_scores;

    cudaFuncSetAttribute(gemm_mma, cudaFuncAttributeMaxDynamicSharedMemorySize, SM_TOTAL);

    // CSR build + weight transpose + zero scores
    zero_kernel<<<(NL * NN + 255) / 256, 256>>>();
    count_kernel<<<(NE + 255) / 256, 256>>>(ei);
    transpose_weights<<<dim3(4, 4, 13), dim3(32, 8)>>>((const float*)d_in[3], (const float*)d_in[7],
                                                       (const float*)d_in[5], (const float*)d_in[9],
                                                       (const float*)d_in[11]);
    scan_kernel<<<1, 1024>>>();
    scatter_kernel<<<(NE + 255) / 256, 256>>>(ei, conf);

    const int GB = (NN + 127) / 128;  // 79 tiles per GEMM
    const float* hin = x;
    for (int i = 0; i < NL; i++) {
        // layer-1 pair: hin -> tmpA (msg), hin -> tmpB (self), both relu
        gemm_mma<<<2 * GB, 512, SM_TOTAL>>>(
            hin, Wt + (long)(0 + i) * DH * DH, msgb1  + i * DH, tmpA, NN, 0,
            hin, Wt + (long)(3 + i) * DH * DH, selfb1 + i * DH, tmpB, NN, 0, GB, nullptr);
        // layer-2 pair: tmpA -> Mh (fp16), tmpB -> Sn (fp32)
        gemm_mma<<<2 * GB, 512, SM_TOTAL>>>(
            tmpA, Wt + (long)(6 + i) * DH * DH, msgb2  + i * DH, Mh, NN, 3,
            tmpB, Wt + (long)(9 + i) * DH * DH, selfb2 + i * DH, Sn, NN, 1, GB, nullptr);
        float* hout = stacked + (long)i * NN * DH;
        aggr_kernel<<<(NN + 7) / 8, 256>>>(hout);
        hin = hout;
    }

    // scoring: fused Linear->ReLU->dot(W2) into GEMM epilogue
    const int GS = (NL * NN + 127) / 128;  // 235 tiles
    gemm_mma<<<GS, 512, SM_TOTAL>>>(
        stacked, Wt + 12L * DH * DH, scoreb1, scores, NL * NN, 2,
        stacked, Wt + 12L * DH * DH, scoreb1, scores, NL * NN, 2, GS, scoreW2);
    final_kernel<<<(NN + 7) / 8, 256>>>(stacked, out, lw);
}